// round 1
// baseline (speedup 1.0000x reference)
#include <cuda_runtime.h>
#include <math.h>

#define Bq 2
#define Lq 1024
#define Aq 14
#define Kq 30
#define NRBF 16
#define NPEq 16
#define EFq 128
#define EDGEIN (NPEq + NRBF*Aq*Aq)   /* 3152 */
#define NE (Bq*Lq*Kq*EFq)            /* 7864320 */
#define NK (Bq*Lq*Kq)                /* 61440 */

__device__ int   g_Eidx[Bq*Lq*Kq];
__device__ float g_Wt[EDGEIN*EFq];

// ---------------------------------------------------------------------------
// Prep: transpose W[f][k] -> Wt[k][f] so GEMM weight loads are coalesced.
// ---------------------------------------------------------------------------
__global__ void transpose_W_kernel(const float* __restrict__ W) {
    int idx = blockIdx.x * blockDim.x + threadIdx.x;
    if (idx < EFq * EDGEIN) {
        int f = idx / EDGEIN, k = idx % EDGEIN;
        g_Wt[k * EFq + f] = W[idx];
    }
}

// ---------------------------------------------------------------------------
// KNN: per (b,i) row, D = m2*sqrt(|dCa|^2+1e-6); D_adjust = D + 2(1-m2)Dmax;
// pick K smallest with (value, index) lexicographic order == jax top_k(-D).
// ---------------------------------------------------------------------------
__global__ void knn_kernel(const float* __restrict__ X,
                           const float* __restrict__ mask,
                           float* __restrict__ outIdxF) {
    const int bi  = blockIdx.x;
    const int b   = bi / Lq;
    const int tid = threadIdx.x;

    __shared__ float sD[Lq];
    __shared__ float smax[8];
    __shared__ unsigned long long red[8];

    const float mi  = mask[bi];
    const float xi0 = X[(bi*Aq + 1)*3 + 0];
    const float xi1 = X[(bi*Aq + 1)*3 + 1];
    const float xi2 = X[(bi*Aq + 1)*3 + 2];

    float lmax = 0.f;
    for (int j = tid; j < Lq; j += 256) {
        const float* xj = X + ((b*Lq + j)*Aq + 1)*3;
        float dx = xi0 - xj[0], dy = xi1 - xj[1], dz = xi2 - xj[2];
        float m2 = mi * mask[b*Lq + j];
        float D  = m2 * sqrtf(dx*dx + dy*dy + dz*dz + 1e-6f);
        sD[j] = D;
        lmax = fmaxf(lmax, D);
    }
    #pragma unroll
    for (int o = 16; o > 0; o >>= 1)
        lmax = fmaxf(lmax, __shfl_xor_sync(0xffffffffu, lmax, o));
    if ((tid & 31) == 0) smax[tid >> 5] = lmax;
    __syncthreads();
    float Dmax = smax[0];
    #pragma unroll
    for (int w = 1; w < 8; w++) Dmax = fmaxf(Dmax, smax[w]);

    for (int j = tid; j < Lq; j += 256) {
        float m2 = mi * mask[b*Lq + j];
        sD[j] += 2.f * (1.f - m2) * Dmax;
    }
    __syncthreads();

    for (int k = 0; k < Kq; k++) {
        unsigned long long best = 0xffffffffffffffffull;
        for (int j = tid; j < Lq; j += 256) {
            unsigned long long p =
                (((unsigned long long)__float_as_uint(sD[j])) << 32) | (unsigned)j;
            best = (p < best) ? p : best;
        }
        #pragma unroll
        for (int o = 16; o > 0; o >>= 1) {
            unsigned long long other = __shfl_xor_sync(0xffffffffu, best, o);
            best = (other < best) ? other : best;
        }
        if ((tid & 31) == 0) red[tid >> 5] = best;
        __syncthreads();
        if (tid == 0) {
            unsigned long long bb = red[0];
            #pragma unroll
            for (int w = 1; w < 8; w++) bb = (red[w] < bb) ? red[w] : bb;
            int j = (int)(bb & 0xffffffffull);
            g_Eidx[bi*Kq + k] = j;
            if (outIdxF) outIdxF[bi*Kq + k] = (float)j;
            sD[j] = __int_as_float(0x7f800000);   // +inf: remove
        }
        __syncthreads();
    }
}

// ---------------------------------------------------------------------------
// Edge features + GEMM + LayerNorm, fused. One block per (b,i) row, 128 thr.
// ---------------------------------------------------------------------------
__device__ __forceinline__ void loadX2(const float* __restrict__ Xres, int a, float* out3) {
    if (a == 4) {  // virtual Cb from N, Ca, C
        float Nx = Xres[0], Ny = Xres[1], Nz = Xres[2];
        float Cax= Xres[3], Cay= Xres[4], Caz= Xres[5];
        float Cx = Xres[6], Cy = Xres[7], Cz = Xres[8];
        float bx = Cax - Nx, by = Cay - Ny, bz = Caz - Nz;
        float cx = Cx - Cax, cy = Cy - Cay, cz = Cz - Caz;
        float ax = by*cz - bz*cy;
        float ay = bz*cx - bx*cz;
        float az = bx*cy - by*cx;
        out3[0] = -0.58273431f*ax + 0.56802827f*bx - 0.54067466f*cx + Cax;
        out3[1] = -0.58273431f*ay + 0.56802827f*by - 0.54067466f*cy + Cay;
        out3[2] = -0.58273431f*az + 0.56802827f*bz - 0.54067466f*cz + Caz;
    } else {
        out3[0] = Xres[a*3+0];
        out3[1] = Xres[a*3+1];
        out3[2] = Xres[a*3+2];
    }
}

__device__ __forceinline__ float dot16(const float* __restrict__ w,
                                       const float* __restrict__ v) {
    const float4* fp = (const float4*)v;
    float4 a0 = fp[0], a1 = fp[1], a2 = fp[2], a3 = fp[3];
    float s;
    s  = w[0]*a0.x;  s = fmaf(w[1],  a0.y, s); s = fmaf(w[2],  a0.z, s); s = fmaf(w[3],  a0.w, s);
    s  = fmaf(w[4],  a1.x, s); s = fmaf(w[5],  a1.y, s); s = fmaf(w[6],  a1.z, s); s = fmaf(w[7],  a1.w, s);
    s  = fmaf(w[8],  a2.x, s); s = fmaf(w[9],  a2.y, s); s = fmaf(w[10], a2.z, s); s = fmaf(w[11], a2.w, s);
    s  = fmaf(w[12], a3.x, s); s = fmaf(w[13], a3.y, s); s = fmaf(w[14], a3.z, s); s = fmaf(w[15], a3.w, s);
    return s;
}

__global__ __launch_bounds__(128) void edge_kernel(
    const float* __restrict__ X,
    const float* __restrict__ atom_mask,
    const float* __restrict__ gamma,
    const float* __restrict__ beta,
    float* __restrict__ outE) {

    const int bi = blockIdx.x;
    const int b  = bi / Lq, i = bi % Lq;
    const int tid = threadIdx.x;

    __shared__ float X2i[Aq][3];
    __shared__ float X2n[Kq][Aq][3];
    __shared__ float ami[Aq];
    __shared__ float amn[Kq][Aq];
    __shared__ int   jn[Kq];
    __shared__ float Dab[Kq][Aq*Aq];
    __shared__ float Epos[Kq][NPEq];
    __shared__ float Fbuf[2][Kq][NRBF];
    __shared__ float redsum[4], redsq[4];

    if (tid < Kq) jn[tid] = g_Eidx[bi*Kq + tid];
    if (tid < Aq) {
        loadX2(X + bi*Aq*3, tid, X2i[tid]);
        ami[tid] = 1.0f - atom_mask[bi*Aq + tid];
    }
    __syncthreads();

    for (int t = tid; t < Kq*Aq; t += 128) {
        int e = t / Aq, a = t % Aq;
        int j = jn[e];
        loadX2(X + (b*Lq + j)*Aq*3, a, X2n[e][a]);
        amn[e][a] = 1.0f - atom_mask[(b*Lq + j)*Aq + a];
    }
    __syncthreads();

    // all pairwise atom distances for the 30 neighbors (cheap: 5880 sqrt/block)
    for (int t = tid; t < Kq*Aq*Aq; t += 128) {
        int e = t / (Aq*Aq), p = t % (Aq*Aq);
        int a = p / Aq, b2 = p % Aq;
        float dx = X2i[a][0] - X2n[e][b2][0];
        float dy = X2i[a][1] - X2n[e][b2][1];
        float dz = X2i[a][2] - X2n[e][b2][2];
        Dab[e][p] = sqrtf(dx*dx + dy*dy + dz*dz + 1e-6f);
    }
    // positional encoding
    for (int t = tid; t < Kq*NPEq; t += 128) {
        int e = t / NPEq, p = t % NPEq;
        float d  = (float)jn[e] - (float)i;
        int   pp = p & 7;
        float fr = expf((float)(2*pp) * -0.57564627324851148f); // -ln(1e4)/16
        float ang = d * fr;
        Epos[e][p] = (p < 8) ? cosf(ang) : sinf(ang);
    }
    __syncthreads();

    const int f = tid;  // one output feature per thread
    float acc[Kq];
    #pragma unroll
    for (int e = 0; e < Kq; e++) acc[e] = 0.f;

    // --- positional-encoding chunk (k = 0..15) ---
    {
        float w[16];
        #pragma unroll
        for (int r = 0; r < 16; r++) w[r] = g_Wt[r*EFq + f];   // coalesced
        #pragma unroll
        for (int e = 0; e < Kq; e++) acc[e] += dot16(w, Epos[e]);
    }

    // --- RBF chunks: iterate (a,b) atom pairs; skip combo==0 blocks exactly ---
    int buf = 0;
    for (int a = 0; a < Aq; a++) {
        if (ami[a] == 0.f) continue;          // uniform across block: skip whole a
        for (int b2 = 0; b2 < Aq; b2++) {
            // produce rbf values for this (a,b2) into the current buffer
            for (int t = tid; t < Kq*NRBF; t += 128) {
                int e = t / NRBF, r = t % NRBF;
                float v = 0.f;
                if (amn[e][b2] != 0.f) {
                    float Dv = Dab[e][a*Aq + b2];
                    float x  = (Dv - (float)r * (20.f/15.f)) * 0.8f; // /sigma=1.25
                    v = __expf(-x*x);
                }
                Fbuf[buf][e][r] = v;
            }
            __syncthreads();   // single barrier per chunk (double-buffered F)

            const int k0 = NPEq + (a*Aq + b2)*NRBF;
            float w[16];
            #pragma unroll
            for (int r = 0; r < 16; r++) w[r] = g_Wt[(k0+r)*EFq + f];  // coalesced L2 hits
            #pragma unroll
            for (int e = 0; e < Kq; e++) {
                if (amn[e][b2] != 0.f) {      // warp-uniform skip (combo==0 exact)
                    acc[e] += dot16(w, Fbuf[buf][e]);
                }
            }
            buf ^= 1;
        }
    }

    // --- LayerNorm over the 128 features (one per thread) + store ---
    const float gamma_f = gamma[f], beta_f = beta[f];
    float* outRow = outE + (size_t)bi * (Kq*EFq);
    for (int e = 0; e < Kq; e++) {
        float v = acc[e];
        float s = v, sq = v*v;
        #pragma unroll
        for (int o = 16; o > 0; o >>= 1) {
            s  += __shfl_xor_sync(0xffffffffu, s,  o);
            sq += __shfl_xor_sync(0xffffffffu, sq, o);
        }
        if ((tid & 31) == 0) { redsum[tid >> 5] = s; redsq[tid >> 5] = sq; }
        __syncthreads();
        float S  = redsum[0] + redsum[1] + redsum[2] + redsum[3];
        float SQ = redsq[0]  + redsq[1]  + redsq[2]  + redsq[3];
        float mean = S  * (1.f/EFq);
        float var  = SQ * (1.f/EFq) - mean*mean;
        outRow[e*EFq + f] = (v - mean) * rsqrtf(var + 1e-5f) * gamma_f + beta_f;
        __syncthreads();
    }
}

// ---------------------------------------------------------------------------
extern "C" void kernel_launch(void* const* d_in, const int* in_sizes, int n_in,
                              void* d_out, int out_size) {
    const float* X         = (const float*)d_in[0];
    const float* mask      = (const float*)d_in[1];
    // d_in[2] residue_idx, d_in[3] chain_labels: unused by the reference math
    const float* atom_mask = (const float*)d_in[4];
    const float* W         = (const float*)d_in[5];
    const float* gamma     = (const float*)d_in[6];
    const float* beta      = (const float*)d_in[7];

    float* outE   = (float*)d_out;
    float* outIdx = (out_size >= NE + NK) ? (outE + NE) : nullptr;

    transpose_W_kernel<<<(EFq*EDGEIN + 255)/256, 256>>>(W);
    knn_kernel<<<Bq*Lq, 256>>>(X, mask, outIdx);
    edge_kernel<<<Bq*Lq, 128>>>(X, atom_mask, gamma, beta, outE);
}